// round 6
// baseline (speedup 1.0000x reference)
#include <cuda_runtime.h>
#include <cuda_bf16.h>
#include <cstdint>
#include <cstddef>

// ============================================================================
// CrystalAttention (sm_100, mma.sync path).
//   e[r,n]  = exp(scales[n]/(dist[r,n]+0.1)),  E'[r,n] = e - C  (bf16)
//   L[r]    = sum_n e[r,n]   (fp32 atomics)
//   VWT     = W @ V^T  [512 x 1024]  (fp32 compute, bf16 store)
//   Y[r,:]  = b + (E' @ VWT^T + C*w1)/L[r],  w1 = (colsum V) @ W^T  (fp32)
// GEMM1: cross = Xb @ Pb^T   (16384 x 1024, K=512) -> exp epilogue -> g_E, g_L
// GEMM2: Y     = E' @ VWT^T  (16384 x 512, K=1024) -> final epilogue -> out
// GEMM tile: 128x256 per CTA, 8 warps (2m x 4n), warp tile 64x64, BK=64,
// 3-stage cp.async pipeline, register double-buffered ldmatrix.
// ============================================================================

#define DEVFN __device__ __forceinline__

constexpr int MROWS = 16384;
constexpr int DDIM  = 512;
constexpr int NNEUR = 1024;
constexpr float C_SHIFT = 1.25f;
constexpr int STG_BYTES = 49152;              // 16K A + 32K B
constexpr int SMEM_SZ = 3 * STG_BYTES;        // 144 KB

__device__ __align__(128) __nv_bfloat16 g_Xb [MROWS * DDIM];
__device__ __align__(128) __nv_bfloat16 g_Pb [NNEUR * DDIM];
__device__ __align__(128) __nv_bfloat16 g_VWT[DDIM * NNEUR];   // (V@W^T)^T = W@V^T
__device__ __align__(128) __nv_bfloat16 g_E  [MROWS * NNEUR];
__device__ float g_xsq  [MROWS];
__device__ float g_psq  [NNEUR];
__device__ float g_vsum4[4][DDIM];
__device__ float g_w1   [DDIM];
__device__ float g_L    [MROWS];

// ----------------------------- prep kernels --------------------------------

template <int WHICH>
__global__ void prep_rows(const float* __restrict__ src) {
    const int r = blockIdx.x, tid = threadIdx.x;       // 128 thr, 4 floats each
    float4 v = reinterpret_cast<const float4*>(src)[(size_t)r * 128 + tid];
    __nv_bfloat16* dst = (WHICH == 0 ? g_Xb : g_Pb) + (size_t)r * 512 + tid * 4;
    __nv_bfloat162 p0, p1;
    p0.x = __float2bfloat16(v.x); p0.y = __float2bfloat16(v.y);
    p1.x = __float2bfloat16(v.z); p1.y = __float2bfloat16(v.w);
    *reinterpret_cast<__nv_bfloat162*>(dst)     = p0;
    *reinterpret_cast<__nv_bfloat162*>(dst + 2) = p1;
    float s = v.x * v.x + v.y * v.y + v.z * v.z + v.w * v.w;
    #pragma unroll
    for (int o = 16; o > 0; o >>= 1) s += __shfl_xor_sync(0xffffffffu, s, o);
    __shared__ float ws[4];
    if ((tid & 31) == 0) ws[tid >> 5] = s;
    __syncthreads();
    if (tid == 0) (WHICH == 0 ? g_xsq : g_psq)[r] = ws[0] + ws[1] + ws[2] + ws[3];
}

__global__ void prep_vsum(const float* __restrict__ values) {
    const int nc = blockIdx.x & 3, dc = blockIdx.x >> 2;
    const int d = dc * 128 + threadIdx.x;
    float s = 0.f;
    for (int n = nc * 256; n < (nc + 1) * 256; n++) s += values[(size_t)n * DDIM + d];
    g_vsum4[nc][d] = s;
}

__global__ void prep_misc(const float* __restrict__ W) {
    const int dp = blockIdx.x, tid = threadIdx.x;
    float p = 0.f;
    #pragma unroll
    for (int j = 0; j < 4; j++) {
        int d = tid + j * 128;
        float vs = g_vsum4[0][d] + g_vsum4[1][d] + g_vsum4[2][d] + g_vsum4[3][d];
        p += vs * W[(size_t)dp * DDIM + d];
    }
    #pragma unroll
    for (int o = 16; o > 0; o >>= 1) p += __shfl_xor_sync(0xffffffffu, p, o);
    __shared__ float ws[4];
    if ((tid & 31) == 0) ws[tid >> 5] = p;
    __syncthreads();
    if (tid == 0) g_w1[dp] = ws[0] + ws[1] + ws[2] + ws[3];
    if (tid < 32) g_L[dp * 32 + tid] = 0.f;
}

// VWT[dp][n] = sum_d W[dp][d] * V[n][d]   (fp32 compute, bf16 store)
__global__ __launch_bounds__(256)
void vw_gemm(const float* __restrict__ V, const float* __restrict__ W) {
    __shared__ float As[16][65];
    __shared__ float Bs[16][65];
    const int tid = threadIdx.x;
    const int m0 = blockIdx.y * 64, n0 = blockIdx.x * 64;
    const int k = tid & 15, rr = tid >> 4;
    const int ty = tid >> 4, tx = tid & 15;

    float acc[4][4] = {};
    for (int kb = 0; kb < 512; kb += 16) {
        #pragma unroll
        for (int i = 0; i < 4; i++) {
            As[k][rr + i * 16] = W[(size_t)(m0 + rr + i * 16) * DDIM + kb + k];
            Bs[k][rr + i * 16] = V[(size_t)(n0 + rr + i * 16) * DDIM + kb + k];
        }
        __syncthreads();
        #pragma unroll
        for (int kk = 0; kk < 16; kk++) {
            float ra[4], rb[4];
            #pragma unroll
            for (int i = 0; i < 4; i++) ra[i] = As[kk][ty * 4 + i];
            #pragma unroll
            for (int j = 0; j < 4; j++) rb[j] = Bs[kk][tx * 4 + j];
            #pragma unroll
            for (int i = 0; i < 4; i++)
                #pragma unroll
                for (int j = 0; j < 4; j++) acc[i][j] += ra[i] * rb[j];
        }
        __syncthreads();
    }
    #pragma unroll
    for (int i = 0; i < 4; i++) {
        #pragma unroll
        for (int j = 0; j < 2; j++) {
            __nv_bfloat162 pv;
            pv.x = __float2bfloat16(acc[i][2 * j]);
            pv.y = __float2bfloat16(acc[i][2 * j + 1]);
            *reinterpret_cast<__nv_bfloat162*>(
                &g_VWT[(size_t)(m0 + ty * 4 + i) * NNEUR + n0 + tx * 4 + 2 * j]) = pv;
        }
    }
}

// ----------------------------- GEMM machinery ------------------------------
DEVFN uint32_t swz(uint32_t o) { return o ^ ((o >> 3) & 0x70u); }
DEVFN uint32_t smem_u32(const void* p) { return (uint32_t)__cvta_generic_to_shared(p); }
DEVFN void cp16(uint32_t d, const void* s) {
    asm volatile("cp.async.cg.shared.global [%0], [%1], 16;\n" :: "r"(d), "l"(s));
}
DEVFN void cp_commit() { asm volatile("cp.async.commit_group;\n"); }
template <int N> DEVFN void cp_wait() { asm volatile("cp.async.wait_group %0;\n" :: "n"(N)); }
DEVFN void ldm4(uint32_t a, uint32_t& r0, uint32_t& r1, uint32_t& r2, uint32_t& r3) {
    asm volatile("ldmatrix.sync.aligned.m8n8.x4.shared.b16 {%0,%1,%2,%3}, [%4];\n"
                 : "=r"(r0), "=r"(r1), "=r"(r2), "=r"(r3) : "r"(a));
}
DEVFN void mma16816(float* c, const uint32_t* a, const uint32_t* b) {
    asm volatile("mma.sync.aligned.m16n8k16.row.col.f32.bf16.bf16.f32 "
                 "{%0,%1,%2,%3}, {%4,%5,%6,%7}, {%8,%9}, {%0,%1,%2,%3};\n"
                 : "+f"(c[0]), "+f"(c[1]), "+f"(c[2]), "+f"(c[3])
                 : "r"(a[0]), "r"(a[1]), "r"(a[2]), "r"(a[3]), "r"(b[0]), "r"(b[1]));
}

// CFG 1: cross = Xb @ Pb^T  (K=512)  -> exp epilogue -> g_E, g_L
// CFG 2: Y     = E' @ VWT^T (K=1024) -> final epilogue -> out
template <int CFG>
__global__ __launch_bounds__(256, 1)
void gemm_k(const float* __restrict__ aux, float* __restrict__ outp) {
    constexpr int K  = (CFG == 2) ? 1024 : 512;
    constexpr int BK = 64, STG = 3;
    constexpr int KT = K / BK;

    const __nv_bfloat16* Ag = (CFG == 1) ? g_Xb : g_E;
    const __nv_bfloat16* Bg = (CFG == 1) ? g_Pb : g_VWT;

    extern __shared__ __align__(1024) char smem[];
    const uint32_t sb = smem_u32(smem);

    const int tid  = threadIdx.x;
    const int row0 = blockIdx.y * 128, col0 = blockIdx.x * 256;
    const __nv_bfloat16* gA = Ag + (size_t)row0 * K;
    const __nv_bfloat16* gB = Bg + (size_t)col0 * K;

    // stage layout: A 128x64 bf16 (16KB) then B 256x64 bf16 (32KB)
    auto load_stage = [&](int s, int kt) {
        const int kb = kt * BK;
        const uint32_t baA = sb + s * STG_BYTES, baB = baA + 16384;
        #pragma unroll
        for (int i = 0; i < 4; i++) {                 // A: 1024 16B chunks
            int idx = tid + i * 256;
            int r = idx >> 3, c = idx & 7;
            uint32_t so = swz((uint32_t)(r * 128 + c * 16));
            cp16(baA + so, gA + (size_t)r * K + kb + c * 8);
        }
        #pragma unroll
        for (int i = 0; i < 8; i++) {                 // B: 2048 16B chunks
            int idx = tid + i * 256;
            int r = idx >> 3, c = idx & 7;
            uint32_t so = swz((uint32_t)(r * 128 + c * 16));
            cp16(baB + so, gB + (size_t)r * K + kb + c * 8);
        }
    };

    const int lane = tid & 31, w = tid >> 5;
    const int wm = w >> 2, wn = w & 3;                // warp tile 64(m) x 64(n)
    const int g = lane >> 2, tg = lane & 3;
    const int a_r  = wm * 64 + (lane & 15);
    const int a_kb = (lane >> 4) * 16;
    const int b_r  = wn * 64 + (lane & 7) + ((lane >> 4) << 3);
    const int b_kb = ((lane >> 3) & 1) * 16;

    float acc[4][8][4];
    #pragma unroll
    for (int i = 0; i < 4; i++)
        #pragma unroll
        for (int j = 0; j < 8; j++)
            #pragma unroll
            for (int q = 0; q < 4; q++) acc[i][j][q] = 0.f;

    uint32_t ra[2][4][4], rb[2][8][2];
    auto lds_frags = [&](uint32_t baA, uint32_t baB, int ks, int buf) {
        #pragma unroll
        for (int mi = 0; mi < 4; mi++) {
            uint32_t ad = baA + swz((uint32_t)((a_r + mi * 16) * 128 + ks * 32 + a_kb));
            ldm4(ad, ra[buf][mi][0], ra[buf][mi][1], ra[buf][mi][2], ra[buf][mi][3]);
        }
        #pragma unroll
        for (int np = 0; np < 4; np++) {
            uint32_t ad = baB + swz((uint32_t)((b_r + np * 16) * 128 + ks * 32 + b_kb));
            ldm4(ad, rb[buf][2 * np][0], rb[buf][2 * np][1],
                     rb[buf][2 * np + 1][0], rb[buf][2 * np + 1][1]);
        }
    };

    load_stage(0, 0); cp_commit();
    load_stage(1, 1); cp_commit();
    cp_wait<1>(); __syncthreads();

    for (int kt = 0; kt < KT; ++kt) {
        if (kt + 2 < KT) load_stage((kt + 2) % STG, kt + 2);
        cp_commit();
        const int s = kt % STG;
        const uint32_t baA = sb + s * STG_BYTES, baB = baA + 16384;
        lds_frags(baA, baB, 0, 0);
        #pragma unroll
        for (int ks = 0; ks < 4; ks++) {
            if (ks < 3) lds_frags(baA, baB, ks + 1, (ks + 1) & 1);
            const int buf = ks & 1;
            #pragma unroll
            for (int mi = 0; mi < 4; mi++)
                #pragma unroll
                for (int nt = 0; nt < 8; nt++)
                    mma16816(acc[mi][nt], ra[buf][mi], rb[buf][nt]);
        }
        cp_wait<1>(); __syncthreads();
    }

    // ---------------- epilogues ----------------
    // acc[mi][nt][j]: row = row0+wm*64+mi*16+g+(j>>1)*8
    //                 col = col0+wn*64+nt*8+2*tg+(j&1)
    if constexpr (CFG == 1) {
        #pragma unroll
        for (int mi = 0; mi < 4; mi++) {
            #pragma unroll
            for (int jr = 0; jr < 2; jr++) {
                const int row = row0 + wm * 64 + mi * 16 + g + jr * 8;
                const float xs = g_xsq[row];
                float rsum = 0.f;
                #pragma unroll
                for (int nt = 0; nt < 8; nt++) {
                    const int col = col0 + wn * 64 + nt * 8 + tg * 2;
                    float ev[2];
                    #pragma unroll
                    for (int jc = 0; jc < 2; jc++) {
                        float cross = acc[mi][nt][jr * 2 + jc];
                        float d2 = xs + g_psq[col + jc] - 2.f * cross;
                        float dist = sqrtf(fmaxf(d2, 0.f));
                        float e = __expf(aux[col + jc] / (dist + 0.1f));
                        rsum += e;
                        ev[jc] = e - C_SHIFT;
                    }
                    __nv_bfloat162 pv;
                    pv.x = __float2bfloat16(ev[0]);
                    pv.y = __float2bfloat16(ev[1]);
                    *reinterpret_cast<__nv_bfloat162*>(&g_E[(size_t)row * NNEUR + col]) = pv;
                }
                rsum += __shfl_xor_sync(0xffffffffu, rsum, 1);
                rsum += __shfl_xor_sync(0xffffffffu, rsum, 2);
                if (tg == 0) atomicAdd(&g_L[row], rsum);
            }
        }
    } else {
        #pragma unroll
        for (int mi = 0; mi < 4; mi++) {
            #pragma unroll
            for (int jr = 0; jr < 2; jr++) {
                const int row = row0 + wm * 64 + mi * 16 + g + jr * 8;
                const float invL = 1.f / g_L[row];
                #pragma unroll
                for (int nt = 0; nt < 8; nt++) {
                    const int col = col0 + wn * 64 + nt * 8 + tg * 2;
                    float y0 = aux[col]     + (C_SHIFT * g_w1[col]     + acc[mi][nt][jr * 2])     * invL;
                    float y1 = aux[col + 1] + (C_SHIFT * g_w1[col + 1] + acc[mi][nt][jr * 2 + 1]) * invL;
                    *reinterpret_cast<float2*>(&outp[(size_t)row * DDIM + col]) = make_float2(y0, y1);
                }
            }
        }
    }
}

// ------------------------------- launch ------------------------------------
extern "C" void kernel_launch(void* const* d_in, const int* in_sizes, int n_in,
                              void* d_out, int out_size) {
    const float* x         = (const float*)d_in[0];
    const float* positions = (const float*)d_in[1];
    const float* scales    = (const float*)d_in[2];
    const float* values    = (const float*)d_in[3];
    const float* W         = (const float*)d_in[4];
    const float* b         = (const float*)d_in[5];
    float* out = (float*)d_out;

    cudaFuncSetAttribute(gemm_k<1>, cudaFuncAttributeMaxDynamicSharedMemorySize, SMEM_SZ);
    cudaFuncSetAttribute(gemm_k<2>, cudaFuncAttributeMaxDynamicSharedMemorySize, SMEM_SZ);

    prep_rows<0><<<MROWS, 128>>>(x);
    prep_rows<1><<<NNEUR, 128>>>(positions);
    prep_vsum<<<16, 128>>>(values);
    prep_misc<<<512, 128>>>(W);
    vw_gemm<<<dim3(16, 8), 256>>>(values, W);

    gemm_k<1><<<dim3(4, 128), 256, SMEM_SZ>>>(scales, nullptr);
    gemm_k<2><<<dim3(2, 128), 256, SMEM_SZ>>>(b, out);
}